// round 4
// baseline (speedup 1.0000x reference)
#include <cuda_runtime.h>
#include <cstdint>

#define T_SEQ 32768
#define HID   512
#define CS    8        // cluster size per direction

// 64 MB scratch for xp = x @ Wx^T + b  (device global: allowed, no runtime alloc)
__device__ float g_xp[(size_t)T_SEQ * HID];

// ---------------------------------------------------------------------------
// Kernel 1: xp[m,n] = sum_k x[m,k] * Wx[n,k] + b[n]   (unchanged)
// ---------------------------------------------------------------------------
#define BM 128
#define BN 128
#define BK 16

__global__ void __launch_bounds__(256) gemm_xp_kernel(
    const float* __restrict__ x, const float* __restrict__ Wx,
    const float* __restrict__ b)
{
    __shared__ float As[BK][BM + 4];
    __shared__ float Bs[BK][BN + 4];
    const int bm  = blockIdx.y * BM;
    const int bn  = blockIdx.x * BN;
    const int tid = threadIdx.x;
    const int tx  = tid & 15;
    const int ty  = tid >> 4;

    float acc[8][8];
#pragma unroll
    for (int i = 0; i < 8; i++)
#pragma unroll
        for (int j = 0; j < 8; j++) acc[i][j] = 0.f;

    for (int k0 = 0; k0 < HID; k0 += BK) {
#pragma unroll
        for (int i = 0; i < 2; i++) {
            int idx = tid * 2 + i;
            int r   = idx >> 2;
            int c4  = (idx & 3) * 4;
            float4 va = *(const float4*)&x [(size_t)(bm + r) * HID + k0 + c4];
            As[c4 + 0][r] = va.x; As[c4 + 1][r] = va.y;
            As[c4 + 2][r] = va.z; As[c4 + 3][r] = va.w;
            float4 vb = *(const float4*)&Wx[(size_t)(bn + r) * HID + k0 + c4];
            Bs[c4 + 0][r] = vb.x; Bs[c4 + 1][r] = vb.y;
            Bs[c4 + 2][r] = vb.z; Bs[c4 + 3][r] = vb.w;
        }
        __syncthreads();
#pragma unroll
        for (int k = 0; k < BK; k++) {
            float a[8], bb[8];
#pragma unroll
            for (int i = 0; i < 8; i++) a[i]  = As[k][ty * 8 + i];
#pragma unroll
            for (int j = 0; j < 8; j++) bb[j] = Bs[k][tx * 8 + j];
#pragma unroll
            for (int i = 0; i < 8; i++)
#pragma unroll
                for (int j = 0; j < 8; j++)
                    acc[i][j] = fmaf(a[i], bb[j], acc[i][j]);
        }
        __syncthreads();
    }

#pragma unroll
    for (int i = 0; i < 8; i++) {
        int m = bm + ty * 8 + i;
#pragma unroll
        for (int j = 0; j < 8; j += 4) {
            int n = bn + tx * 8 + j;
            float4 v;
            v.x = acc[i][j + 0] + b[n + 0];
            v.y = acc[i][j + 1] + b[n + 1];
            v.z = acc[i][j + 2] + b[n + 2];
            v.w = acc[i][j + 3] + b[n + 3];
            *(float4*)&g_xp[(size_t)m * HID + n] = v;
        }
    }
}

// ---------------------------------------------------------------------------
// Kernel 2: recurrent scans. 2 clusters x 8 CTAs x 512 threads.
// Publish path (R4): warp-aggregated. Lanes 0 and 16 of each warp send one
// packed st.async.b64 (2 h values) per rank -> 256 messages/CTA/step instead
// of 512, halving DSMEM message + receiver mbarrier-update pressure.
// ---------------------------------------------------------------------------
__device__ __forceinline__ uint32_t smem_u32(const void* p) {
    uint32_t a;
    asm("{ .reg .u64 t; cvta.to.shared.u64 t, %1; cvt.u32.u64 %0, t; }"
        : "=r"(a) : "l"(p));
    return a;
}

#define MBAR_INIT(addr, cnt) \
    asm volatile("mbarrier.init.shared.b64 [%0], %1;" :: "r"(addr), "r"(cnt) : "memory")

// arrive (count 1) + add expected transaction bytes for the current phase
#define MBAR_ARRIVE_EXPECT_TX(addr, tx) \
    asm volatile("mbarrier.arrive.expect_tx.shared.b64 _, [%0], %1;" \
                 :: "r"(addr), "r"(tx) : "memory")

#define MBAR_WAIT(addr, ph) do {                                               \
    uint32_t _done;                                                            \
    asm volatile("{\n\t.reg .pred p;\n\t"                                      \
        "mbarrier.try_wait.parity.acquire.cta.shared::cta.b64 p, [%1], %2;\n\t"\
        "selp.b32 %0, 1, 0, p;\n\t}"                                           \
        : "=r"(_done) : "r"(addr), "r"(ph) : "memory");                        \
    if (!_done) {                                                              \
        asm volatile("{\n\t.reg .pred P1;\n\t"                                 \
            "WL_%=:\n\t"                                                       \
            "mbarrier.try_wait.parity.acquire.cta.shared::cta.b64 P1, [%0], %1, 0x989680;\n\t" \
            "@P1 bra.uni WD_%=;\n\t"                                           \
            "bra.uni WL_%=;\n\t"                                               \
            "WD_%=:\n\t}"                                                      \
            :: "r"(addr), "r"(ph) : "memory");                                 \
    }                                                                          \
} while (0)

#define HPAD 544   // 8 chunks * 68 words: word = col + 4*(col/64), conflict-free

__global__ void __launch_bounds__(512, 1) __cluster_dims__(CS, 1, 1)
scan_kernel(const float* __restrict__ Wh, float* __restrict__ out)
{
    __shared__ alignas(16) float hs[2][HPAD];
    __shared__ alignas(8) unsigned long long mbar[2];

    const int tid       = threadIdx.x;
    const int dir       = blockIdx.x / CS;   // 0 = forward, 1 = reverse
    const int rk        = blockIdx.x % CS;   // cluster rank
    const int row_local = tid >> 3;          // 0..63
    const int sub       = tid & 7;           // 0..7 (column chunk)
    const int row       = rk * 64 + row_local;
    const int lane      = tid & 31;

    // ---- weights into registers as f32x2 pairs: 4 independent chains ----
    unsigned long long w2[32];
    {
        const ulonglong2* wp =
            (const ulonglong2*)&Wh[(size_t)row * HID + sub * 64];
#pragma unroll
        for (int i = 0; i < 16; i++) {
            ulonglong2 v = wp[i];
            w2[2 * i]     = v.x;
            w2[2 * i + 1] = v.y;
        }
    }

    // ---- zero both h buffers (h0 = 0) ----
    for (int i = tid; i < 2 * HPAD; i += 512) ((float*)hs)[i] = 0.f;

    const uint32_t buf0  = smem_u32(&hs[0][0]);
    const uint32_t mb    = smem_u32(&mbar[0]);
    const uint32_t mbrel = mb - buf0;        // mbar offset relative to hs base

    // DSMEM addressing is linear in local offset -> one mapa per rank serves
    // both buffers and both mbarriers.
    uint32_t rank_base[CS];
#pragma unroll
    for (int r = 0; r < CS; r++) {
        asm("mapa.shared::cluster.u32 %0, %1, %2;"
            : "=r"(rank_base[r]) : "r"(buf0), "r"(r));
    }

    if (tid == 0) {
        MBAR_INIT(mb,     1u);
        MBAR_INIT(mb + 8, 1u);
        // pre-arm both phases' arrivals + tx expectations
        MBAR_ARRIVE_EXPECT_TX(mb,     2048u);
        MBAR_ARRIVE_EXPECT_TX(mb + 8, 2048u);
    }
    __syncthreads();
    // all CTAs: buffers zeroed + mbars armed before any remote st.async
    asm volatile("barrier.cluster.arrive.aligned;" ::: "memory");
    asm volatile("barrier.cluster.wait.aligned;"   ::: "memory");

    float* out_h = out + 512 + (size_t)dir * T_SEQ * HID;

    // Sender lanes: lane 0 carries rows {4w, 4w+1}, lane 16 rows {4w+2, 4w+3}.
    const int  warp      = tid >> 5;
    const int  hi_half   = (lane & 16) ? 1 : 0;
    const int  row_send  = rk * 64 + 4 * warp + 2 * hi_half;     // first row in my pair
    const uint32_t send_base =
        ((uint32_t)(68 * rk + 4 * warp) + 2u * (uint32_t)hi_half) * 4u;

    // ---- xp software pipeline (depth 2) ----
    float xp0, xp1;
    {
        size_t i0 = (size_t)(dir ? (T_SEQ - 1) : 0) * HID + row;
        size_t i1 = (size_t)(dir ? (T_SEQ - 2) : 1) * HID + row;
        xp0 = g_xp[i0];
        xp1 = g_xp[i1];
    }

    int ph0 = 0, ph1 = 0;

    for (int t = 0; t < T_SEQ; t++) {
        float xpn = 0.f;
        if (t + 2 < T_SEQ) {
            size_t ii = (size_t)(dir ? (T_SEQ - 3 - t) : (t + 2)) * HID + row;
            xpn = __ldg(&g_xp[ii]);
        }

        const int cur = t & 1;
        if (t > 0) {
            if (cur) {
                MBAR_WAIT(mb + 8, ph1); ph1 ^= 1;
                // re-arm this mbar for its next phase (t+2 data). Early peer
                // tx are absorbed (tx-count may go transiently negative).
                if (tid == 0 && t + 2 < T_SEQ)
                    MBAR_ARRIVE_EXPECT_TX(mb + 8, 2048u);
            } else {
                MBAR_WAIT(mb, ph0); ph0 ^= 1;
                if (tid == 0 && t + 2 < T_SEQ)
                    MBAR_ARRIVE_EXPECT_TX(mb, 2048u);
            }
        }

        // ---- partial matvec: 64 cols, 4 independent f32x2 FMA chains ----
        const float* hp = &hs[cur][68 * sub];
        unsigned long long a0 = 0ull, a1 = 0ull, a2 = 0ull, a3 = 0ull;
#pragma unroll
        for (int k = 0; k < 8; k++) {
            ulonglong2 hA = *(const ulonglong2*)(hp + 8 * k);
            ulonglong2 hB = *(const ulonglong2*)(hp + 8 * k + 4);
            asm("fma.rn.f32x2 %0, %1, %2, %3;"
                : "=l"(a0) : "l"(w2[4 * k + 0]), "l"(hA.x), "l"(a0));
            asm("fma.rn.f32x2 %0, %1, %2, %3;"
                : "=l"(a1) : "l"(w2[4 * k + 1]), "l"(hA.y), "l"(a1));
            asm("fma.rn.f32x2 %0, %1, %2, %3;"
                : "=l"(a2) : "l"(w2[4 * k + 2]), "l"(hB.x), "l"(a2));
            asm("fma.rn.f32x2 %0, %1, %2, %3;"
                : "=l"(a3) : "l"(w2[4 * k + 3]), "l"(hB.y), "l"(a3));
        }
        uint32_t l0, h0, l1, h1, l2, h2, l3, h3;
        asm("mov.b64 {%0,%1}, %2;" : "=r"(l0), "=r"(h0) : "l"(a0));
        asm("mov.b64 {%0,%1}, %2;" : "=r"(l1), "=r"(h1) : "l"(a1));
        asm("mov.b64 {%0,%1}, %2;" : "=r"(l2), "=r"(h2) : "l"(a2));
        asm("mov.b64 {%0,%1}, %2;" : "=r"(l3), "=r"(h3) : "l"(a3));
        float s = ((__uint_as_float(l0) + __uint_as_float(h0))
                 + (__uint_as_float(l1) + __uint_as_float(h1)))
                + ((__uint_as_float(l2) + __uint_as_float(h2))
                 + (__uint_as_float(l3) + __uint_as_float(h3)));

        // reduce across the 8 sub-threads of this row
        s += __shfl_xor_sync(0xffffffffu, s, 1);
        s += __shfl_xor_sync(0xffffffffu, s, 2);
        s += __shfl_xor_sync(0xffffffffu, s, 4);

        float z = s + xp0;
        // fast accurate tanh: h = 1 - 2/(exp(2z)+1), via ex2/rcp MUFU
        float e, r;
        asm("ex2.approx.f32 %0, %1;" : "=f"(e) : "f"(z * 2.885390082f));
        asm("rcp.approx.f32 %0, %1;" : "=f"(r) : "f"(e + 1.0f));
        float h = fmaf(-2.0f, r, 1.0f);

        // gather my 2-row pair: lane<16 -> rows at lanes {0,8}; lane>=16 -> {16,24}
        const int gsrc = lane & 16;
        float ga = __shfl_sync(0xffffffffu, h, gsrc);
        float gb = __shfl_sync(0xffffffffu, h, gsrc + 8);

        if ((tid & 15) == 0) {   // lanes 0 and 16 of each warp
            unsigned long long pk;
            asm("mov.b64 %0, {%1,%2};" : "=l"(pk) : "f"(ga), "f"(gb));
            if (t + 1 < T_SEQ) {
                const uint32_t doff = send_base + (cur ? 0u : (uint32_t)HPAD * 4u);
                const uint32_t moff = mbrel + (cur ? 0u : 8u);
#pragma unroll
                for (int pr = 0; pr < CS; pr++) {
                    asm volatile(
                        "st.async.weak.shared::cluster.mbarrier::complete_tx::bytes.b64 "
                        "[%0], %1, [%2];"
                        :: "r"(rank_base[pr] + doff), "l"(pk),
                           "r"(rank_base[pr] + moff) : "memory");
                }
            }
            *(float2*)&out_h[(size_t)t * HID + row_send] = make_float2(ga, gb);
        }

        xp0 = xp1;
        xp1 = xpn;
    }
}

// ---------------------------------------------------------------------------
// Kernel 3: y = Wout @ concat(h_fwd[-1], h_rev[-1]) + bout   (unchanged)
// ---------------------------------------------------------------------------
__global__ void __launch_bounds__(256) readout_kernel(
    const float* __restrict__ Wout, const float* __restrict__ bout,
    float* __restrict__ out)
{
    const int j = blockIdx.x;
    const float* hf = out + 512 + (size_t)(T_SEQ - 1) * HID;
    const float* hr = out + 512 + (size_t)T_SEQ * HID + (size_t)(T_SEQ - 1) * HID;
    const float* wr = Wout + (size_t)j * (2 * HID);

    float s = 0.f;
    for (int i = threadIdx.x; i < HID; i += 256) s = fmaf(wr[i],       hf[i], s);
    for (int i = threadIdx.x; i < HID; i += 256) s = fmaf(wr[HID + i], hr[i], s);

#pragma unroll
    for (int o = 16; o > 0; o >>= 1) s += __shfl_xor_sync(0xffffffffu, s, o);

    __shared__ float red[8];
    if ((threadIdx.x & 31) == 0) red[threadIdx.x >> 5] = s;
    __syncthreads();
    if (threadIdx.x == 0) {
        float tot = 0.f;
#pragma unroll
        for (int i = 0; i < 8; i++) tot += red[i];
        out[j] = tot + bout[j];
    }
}

// ---------------------------------------------------------------------------
extern "C" void kernel_launch(void* const* d_in, const int* in_sizes, int n_in,
                              void* d_out, int out_size)
{
    const float* x    = (const float*)d_in[0];
    const float* Wx   = (const float*)d_in[1];
    const float* Wh   = (const float*)d_in[2];
    const float* b    = (const float*)d_in[3];
    const float* Wout = (const float*)d_in[4];
    const float* bout = (const float*)d_in[5];
    float* out = (float*)d_out;

    dim3 ggrid(HID / BN, T_SEQ / BM);           // (4, 256)
    gemm_xp_kernel<<<ggrid, 256>>>(x, Wx, b);

    scan_kernel<<<2 * CS, 512>>>(Wh, out);      // 2 clusters of 8 CTAs

    readout_kernel<<<HID, 256>>>(Wout, bout, out);
}

// round 5
// speedup vs baseline: 1.5276x; 1.5276x over previous
#include <cuda_runtime.h>
#include <cstdint>

#define T_SEQ 32768
#define HID   512
#define CS    16       // cluster size per direction (nonportable, 2 clusters)
#define NTHR  256      // threads per scan CTA

// 64 MB scratch for xp = x @ Wx^T + b  (device global: allowed, no runtime alloc)
__device__ float g_xp[(size_t)T_SEQ * HID];

// ---------------------------------------------------------------------------
// Kernel 1: xp[m,n] = sum_k x[m,k] * Wx[n,k] + b[n]   (unchanged)
// ---------------------------------------------------------------------------
#define BM 128
#define BN 128
#define BK 16

__global__ void __launch_bounds__(256) gemm_xp_kernel(
    const float* __restrict__ x, const float* __restrict__ Wx,
    const float* __restrict__ b)
{
    __shared__ float As[BK][BM + 4];
    __shared__ float Bs[BK][BN + 4];
    const int bm  = blockIdx.y * BM;
    const int bn  = blockIdx.x * BN;
    const int tid = threadIdx.x;
    const int tx  = tid & 15;
    const int ty  = tid >> 4;

    float acc[8][8];
#pragma unroll
    for (int i = 0; i < 8; i++)
#pragma unroll
        for (int j = 0; j < 8; j++) acc[i][j] = 0.f;

    for (int k0 = 0; k0 < HID; k0 += BK) {
#pragma unroll
        for (int i = 0; i < 2; i++) {
            int idx = tid * 2 + i;
            int r   = idx >> 2;
            int c4  = (idx & 3) * 4;
            float4 va = *(const float4*)&x [(size_t)(bm + r) * HID + k0 + c4];
            As[c4 + 0][r] = va.x; As[c4 + 1][r] = va.y;
            As[c4 + 2][r] = va.z; As[c4 + 3][r] = va.w;
            float4 vb = *(const float4*)&Wx[(size_t)(bn + r) * HID + k0 + c4];
            Bs[c4 + 0][r] = vb.x; Bs[c4 + 1][r] = vb.y;
            Bs[c4 + 2][r] = vb.z; Bs[c4 + 3][r] = vb.w;
        }
        __syncthreads();
#pragma unroll
        for (int k = 0; k < BK; k++) {
            float a[8], bb[8];
#pragma unroll
            for (int i = 0; i < 8; i++) a[i]  = As[k][ty * 8 + i];
#pragma unroll
            for (int j = 0; j < 8; j++) bb[j] = Bs[k][tx * 8 + j];
#pragma unroll
            for (int i = 0; i < 8; i++)
#pragma unroll
                for (int j = 0; j < 8; j++)
                    acc[i][j] = fmaf(a[i], bb[j], acc[i][j]);
        }
        __syncthreads();
    }

#pragma unroll
    for (int i = 0; i < 8; i++) {
        int m = bm + ty * 8 + i;
#pragma unroll
        for (int j = 0; j < 8; j += 4) {
            int n = bn + tx * 8 + j;
            float4 v;
            v.x = acc[i][j + 0] + b[n + 0];
            v.y = acc[i][j + 1] + b[n + 1];
            v.z = acc[i][j + 2] + b[n + 2];
            v.w = acc[i][j + 3] + b[n + 3];
            *(float4*)&g_xp[(size_t)m * HID + n] = v;
        }
    }
}

// ---------------------------------------------------------------------------
// Kernel 2: recurrent scans. 2 clusters x 16 CTAs x 256 threads.
// Each CTA owns 32 rows; thread (row_local, sub) handles row rk*32+row_local,
// cols [64*sub, 64*sub+64). Publish path = R3's per-thread 4B st.async to all
// 16 ranks' next-phase buffer, signaling the receiver's ping-pong mbarrier.
// ---------------------------------------------------------------------------
__device__ __forceinline__ uint32_t smem_u32(const void* p) {
    uint32_t a;
    asm("{ .reg .u64 t; cvta.to.shared.u64 t, %1; cvt.u32.u64 %0, t; }"
        : "=r"(a) : "l"(p));
    return a;
}

#define MBAR_INIT(addr, cnt) \
    asm volatile("mbarrier.init.shared.b64 [%0], %1;" :: "r"(addr), "r"(cnt) : "memory")

#define MBAR_ARRIVE_EXPECT_TX(addr, tx) \
    asm volatile("mbarrier.arrive.expect_tx.shared.b64 _, [%0], %1;" \
                 :: "r"(addr), "r"(tx) : "memory")

#define MBAR_WAIT(addr, ph) do {                                               \
    uint32_t _done;                                                            \
    asm volatile("{\n\t.reg .pred p;\n\t"                                      \
        "mbarrier.try_wait.parity.acquire.cta.shared::cta.b64 p, [%1], %2;\n\t"\
        "selp.b32 %0, 1, 0, p;\n\t}"                                           \
        : "=r"(_done) : "r"(addr), "r"(ph) : "memory");                        \
    if (!_done) {                                                              \
        asm volatile("{\n\t.reg .pred P1;\n\t"                                 \
            "WL_%=:\n\t"                                                       \
            "mbarrier.try_wait.parity.acquire.cta.shared::cta.b64 P1, [%0], %1, 0x989680;\n\t" \
            "@P1 bra.uni WD_%=;\n\t"                                           \
            "bra.uni WL_%=;\n\t"                                               \
            "WD_%=:\n\t}"                                                      \
            :: "r"(addr), "r"(ph) : "memory");                                 \
    }                                                                          \
} while (0)

#define HPAD 544   // 8 chunks * 68 words: word = col + 4*(col/64), conflict-free

__global__ void __launch_bounds__(NTHR, 1)
scan_kernel(const float* __restrict__ Wh, float* __restrict__ out)
{
    __shared__ alignas(16) float hs[2][HPAD];
    __shared__ alignas(8) unsigned long long mbar[2];

    const int tid       = threadIdx.x;
    const int dir       = blockIdx.x / CS;   // 0 = forward, 1 = reverse
    const int rk        = blockIdx.x % CS;   // cluster rank
    const int row_local = tid >> 3;          // 0..31
    const int sub       = tid & 7;           // 0..7 (64-col chunk)
    const int row       = rk * 32 + row_local;

    // ---- weights into registers as f32x2 pairs: 4 independent chains ----
    unsigned long long w2[32];
    {
        const ulonglong2* wp =
            (const ulonglong2*)&Wh[(size_t)row * HID + sub * 64];
#pragma unroll
        for (int i = 0; i < 16; i++) {
            ulonglong2 v = wp[i];
            w2[2 * i]     = v.x;
            w2[2 * i + 1] = v.y;
        }
    }

    // ---- zero both h buffers (h0 = 0) ----
    for (int i = tid; i < 2 * HPAD; i += NTHR) ((float*)hs)[i] = 0.f;

    const uint32_t buf0  = smem_u32(&hs[0][0]);
    const uint32_t mb    = smem_u32(&mbar[0]);
    const uint32_t mbrel = mb - buf0;        // mbar offset relative to hs base

    // DSMEM addressing is linear in local offset -> one mapa per rank serves
    // both buffers and both mbarriers.
    uint32_t rank_base[CS];
#pragma unroll
    for (int r = 0; r < CS; r++) {
        asm("mapa.shared::cluster.u32 %0, %1, %2;"
            : "=r"(rank_base[r]) : "r"(buf0), "r"(r));
    }

    if (tid == 0) {
        MBAR_INIT(mb,     1u);
        MBAR_INIT(mb + 8, 1u);
        // pre-arm both phases' arrivals + tx expectations (512 msgs x 4B)
        MBAR_ARRIVE_EXPECT_TX(mb,     2048u);
        MBAR_ARRIVE_EXPECT_TX(mb + 8, 2048u);
    }
    __syncthreads();
    // all CTAs: buffers zeroed + mbars armed before any remote st.async
    asm volatile("barrier.cluster.arrive.aligned;" ::: "memory");
    asm volatile("barrier.cluster.wait.aligned;"   ::: "memory");

    float* out_h = out + 512 + (size_t)dir * T_SEQ * HID;

    // destination offsets for my h value: global row = rk*32+row_local sits in
    // 64-col chunk (rk>>1), word 68*(rk>>1) + 32*(rk&1) + row_local.
    const uint32_t doff0 =
        (uint32_t)(68 * (rk >> 1) + 32 * (rk & 1) + row_local) * 4u;
    const uint32_t doff1 = doff0 + (uint32_t)HPAD * 4u;

    // ---- xp software pipeline (depth 2) ----
    float xp0, xp1;
    {
        size_t i0 = (size_t)(dir ? (T_SEQ - 1) : 0) * HID + row;
        size_t i1 = (size_t)(dir ? (T_SEQ - 2) : 1) * HID + row;
        xp0 = g_xp[i0];
        xp1 = g_xp[i1];
    }

    int ph0 = 0, ph1 = 0;

    for (int t = 0; t < T_SEQ; t++) {
        float xpn = 0.f;
        if (t + 2 < T_SEQ) {
            size_t ii = (size_t)(dir ? (T_SEQ - 3 - t) : (t + 2)) * HID + row;
            xpn = __ldg(&g_xp[ii]);
        }

        const int cur = t & 1;
        if (t > 0) {
            if (cur) {
                MBAR_WAIT(mb + 8, ph1); ph1 ^= 1;
                // re-arm this mbar for its next phase (t+2 data). Early peer
                // tx are absorbed (tx-count may go transiently negative).
                if (tid == 0 && t + 2 < T_SEQ)
                    MBAR_ARRIVE_EXPECT_TX(mb + 8, 2048u);
            } else {
                MBAR_WAIT(mb, ph0); ph0 ^= 1;
                if (tid == 0 && t + 2 < T_SEQ)
                    MBAR_ARRIVE_EXPECT_TX(mb, 2048u);
            }
        }

        // ---- partial matvec: 64 cols, 4 independent f32x2 FMA chains ----
        const float* hp = &hs[cur][68 * sub];
        unsigned long long a0 = 0ull, a1 = 0ull, a2 = 0ull, a3 = 0ull;
#pragma unroll
        for (int k = 0; k < 8; k++) {
            ulonglong2 hA = *(const ulonglong2*)(hp + 8 * k);
            ulonglong2 hB = *(const ulonglong2*)(hp + 8 * k + 4);
            asm("fma.rn.f32x2 %0, %1, %2, %3;"
                : "=l"(a0) : "l"(w2[4 * k + 0]), "l"(hA.x), "l"(a0));
            asm("fma.rn.f32x2 %0, %1, %2, %3;"
                : "=l"(a1) : "l"(w2[4 * k + 1]), "l"(hA.y), "l"(a1));
            asm("fma.rn.f32x2 %0, %1, %2, %3;"
                : "=l"(a2) : "l"(w2[4 * k + 2]), "l"(hB.x), "l"(a2));
            asm("fma.rn.f32x2 %0, %1, %2, %3;"
                : "=l"(a3) : "l"(w2[4 * k + 3]), "l"(hB.y), "l"(a3));
        }
        uint32_t l0, h0, l1, h1, l2, h2, l3, h3;
        asm("mov.b64 {%0,%1}, %2;" : "=r"(l0), "=r"(h0) : "l"(a0));
        asm("mov.b64 {%0,%1}, %2;" : "=r"(l1), "=r"(h1) : "l"(a1));
        asm("mov.b64 {%0,%1}, %2;" : "=r"(l2), "=r"(h2) : "l"(a2));
        asm("mov.b64 {%0,%1}, %2;" : "=r"(l3), "=r"(h3) : "l"(a3));
        float s = ((__uint_as_float(l0) + __uint_as_float(h0))
                 + (__uint_as_float(l1) + __uint_as_float(h1)))
                + ((__uint_as_float(l2) + __uint_as_float(h2))
                 + (__uint_as_float(l3) + __uint_as_float(h3)));

        // reduce across the 8 sub-threads of this row
        s += __shfl_xor_sync(0xffffffffu, s, 1);
        s += __shfl_xor_sync(0xffffffffu, s, 2);
        s += __shfl_xor_sync(0xffffffffu, s, 4);

        float z = s + xp0;
        // fast accurate tanh: h = 1 - 2/(exp(2z)+1), via ex2/rcp MUFU
        float e, r;
        asm("ex2.approx.f32 %0, %1;" : "=f"(e) : "f"(z * 2.885390082f));
        asm("rcp.approx.f32 %0, %1;" : "=f"(r) : "f"(e + 1.0f));
        float h = fmaf(-2.0f, r, 1.0f);

        if (sub == 0) {
            if (t + 1 < T_SEQ) {
                // publish h to every rank's next-phase buffer (incl. self)
                const uint32_t doff = cur ? doff0 : doff1;   // dest buf = cur^1
                const uint32_t moff = mbrel + (cur ? 0u : 8u);
#pragma unroll
                for (int pr = 0; pr < CS; pr++) {
                    asm volatile(
                        "st.async.weak.shared::cluster.mbarrier::complete_tx::bytes.f32 "
                        "[%0], %1, [%2];"
                        :: "r"(rank_base[pr] + doff), "f"(h),
                           "r"(rank_base[pr] + moff) : "memory");
                }
            }
            out_h[(size_t)t * HID + row] = h;
        }

        xp0 = xp1;
        xp1 = xpn;
    }
}

// ---------------------------------------------------------------------------
// Kernel 3: y = Wout @ concat(h_fwd[-1], h_rev[-1]) + bout   (unchanged)
// ---------------------------------------------------------------------------
__global__ void __launch_bounds__(256) readout_kernel(
    const float* __restrict__ Wout, const float* __restrict__ bout,
    float* __restrict__ out)
{
    const int j = blockIdx.x;
    const float* hf = out + 512 + (size_t)(T_SEQ - 1) * HID;
    const float* hr = out + 512 + (size_t)T_SEQ * HID + (size_t)(T_SEQ - 1) * HID;
    const float* wr = Wout + (size_t)j * (2 * HID);

    float s = 0.f;
    for (int i = threadIdx.x; i < HID; i += 256) s = fmaf(wr[i],       hf[i], s);
    for (int i = threadIdx.x; i < HID; i += 256) s = fmaf(wr[HID + i], hr[i], s);

#pragma unroll
    for (int o = 16; o > 0; o >>= 1) s += __shfl_xor_sync(0xffffffffu, s, o);

    __shared__ float red[8];
    if ((threadIdx.x & 31) == 0) red[threadIdx.x >> 5] = s;
    __syncthreads();
    if (threadIdx.x == 0) {
        float tot = 0.f;
#pragma unroll
        for (int i = 0; i < 8; i++) tot += red[i];
        out[j] = tot + bout[j];
    }
}

// ---------------------------------------------------------------------------
extern "C" void kernel_launch(void* const* d_in, const int* in_sizes, int n_in,
                              void* d_out, int out_size)
{
    const float* x    = (const float*)d_in[0];
    const float* Wx   = (const float*)d_in[1];
    const float* Wh   = (const float*)d_in[2];
    const float* b    = (const float*)d_in[3];
    const float* Wout = (const float*)d_in[4];
    const float* bout = (const float*)d_in[5];
    float* out = (float*)d_out;

    dim3 ggrid(HID / BN, T_SEQ / BM);           // (4, 256)
    gemm_xp_kernel<<<ggrid, 256>>>(x, Wx, b);

    // 2 clusters of 16 CTAs (nonportable cluster size)
    cudaFuncSetAttribute(scan_kernel,
                         cudaFuncAttributeNonPortableClusterSizeAllowed, 1);
    cudaLaunchConfig_t cfg = {};
    cfg.gridDim  = dim3(2 * CS, 1, 1);
    cfg.blockDim = dim3(NTHR, 1, 1);
    cfg.dynamicSmemBytes = 0;
    cfg.stream = 0;
    cudaLaunchAttribute attrs[1];
    attrs[0].id = cudaLaunchAttributeClusterDimension;
    attrs[0].val.clusterDim = {CS, 1, 1};
    cfg.attrs = attrs;
    cfg.numAttrs = 1;
    cudaLaunchKernelEx(&cfg, scan_kernel, Wh, out);

    readout_kernel<<<HID, 256>>>(Wout, bout, out);
}